// round 2
// baseline (speedup 1.0000x reference)
#include <cuda_runtime.h>

#define NHEADS   8
#define DK       64
#define SEQ      1024
#define BATCH    8
#define DMODEL   512
#define BHD      (BATCH*NHEADS)          // 64
#define TOKENS   (BATCH*SEQ)             // 8192
#define QKV_ELEMS (BHD*SEQ*DK)           // 4194304

// ---------------- scratch (device globals; no allocation allowed) ----------
__device__ float g_q[QKV_ELEMS];
__device__ float g_k[QKV_ELEMS];
__device__ float g_v[QKV_ELEMS];
__device__ float g_nq[QKV_ELEMS];
__device__ float g_ssq;

// ---------------------------------------------------------------------------
// QKV projection: out = x @ W + b, written directly into (B,H,S,64) layout.
// Tiled 64x64x16 fp32 GEMM, 256 threads, 4x4 microtile per thread.
// grid = (TOKENS/64, 24)  [blockIdx.y: mat*8 + ntile, ntile == head]
// ---------------------------------------------------------------------------
__global__ __launch_bounds__(256)
void qkv_gemm(const float* __restrict__ x,
              const float* __restrict__ Wq, const float* __restrict__ bq,
              const float* __restrict__ Wk, const float* __restrict__ bk,
              const float* __restrict__ Wv, const float* __restrict__ bv)
{
    __shared__ float As[16][64];   // [k][m]
    __shared__ float Bs[16][64];   // [k][n]

    const int mat   = blockIdx.y >> 3;     // 0=q,1=k,2=v
    const int ntile = blockIdx.y & 7;      // head index (BN=64 == head dim)
    const int row0  = blockIdx.x * 64;

    const float* W    = (mat == 0) ? Wq : (mat == 1) ? Wk : Wv;
    const float* bias = (mat == 0) ? bq : (mat == 1) ? bk : bv;
    float*       out  = (mat == 0) ? g_q : (mat == 1) ? g_k : g_v;

    const int tid = threadIdx.x;
    const int tx = tid & 15, ty = tid >> 4;

    const int ar = tid >> 2;          // 0..63 (m within tile)
    const int ac = (tid & 3) * 4;     // 0,4,8,12 (k within tile)
    const int br = tid >> 4;          // 0..15 (k within tile)
    const int bc = (tid & 15) * 4;    // 0..60 (n within tile)

    float acc[4][4] = {};

    for (int k0 = 0; k0 < DMODEL; k0 += 16) {
        float4 av = *(const float4*)(x + (size_t)(row0 + ar) * DMODEL + k0 + ac);
        As[ac + 0][ar] = av.x; As[ac + 1][ar] = av.y;
        As[ac + 2][ar] = av.z; As[ac + 3][ar] = av.w;
        float4 b4 = *(const float4*)(W + (size_t)(k0 + br) * DMODEL + ntile * 64 + bc);
        *(float4*)&Bs[br][bc] = b4;
        __syncthreads();
        #pragma unroll
        for (int kk = 0; kk < 16; kk++) {
            float4 a4 = *(float4*)&As[kk][ty * 4];
            float4 bb4 = *(float4*)&Bs[kk][tx * 4];
            float aa[4] = {a4.x, a4.y, a4.z, a4.w};
            float bb[4] = {bb4.x, bb4.y, bb4.z, bb4.w};
            #pragma unroll
            for (int i = 0; i < 4; i++)
                #pragma unroll
                for (int j = 0; j < 4; j++)
                    acc[i][j] += aa[i] * bb[j];
        }
        __syncthreads();
    }

    float4 bia = *(const float4*)(bias + ntile * 64 + tx * 4);
    #pragma unroll
    for (int i = 0; i < 4; i++) {
        int t = row0 + ty * 4 + i;
        int b = t >> 10, s = t & 1023;
        float* orow = out + (((size_t)b * NHEADS + ntile) * SEQ + s) * DK;
        float4 v4;
        v4.x = acc[i][0] + bia.x; v4.y = acc[i][1] + bia.y;
        v4.z = acc[i][2] + bia.z; v4.w = acc[i][3] + bia.w;
        *(float4*)&orow[tx * 4] = v4;
    }
}

// ---------------------------------------------------------------------------
// LayerNorm over last dim (64) for q and k. One warp per row.
// grid*block covers 2*BHD*SEQ warps.
// ---------------------------------------------------------------------------
__global__ __launch_bounds__(256)
void ln_kernel(const float* __restrict__ gamma, const float* __restrict__ beta)
{
    int warp = (blockIdx.x * blockDim.x + threadIdx.x) >> 5;
    int lane = threadIdx.x & 31;
    float* buf = (warp < BHD * SEQ) ? g_q : g_k;
    int r = (warp < BHD * SEQ) ? warp : warp - BHD * SEQ;
    float* p = buf + (size_t)r * DK;

    float v0 = p[lane], v1 = p[lane + 32];
    float sum = v0 + v1;
    #pragma unroll
    for (int o = 16; o; o >>= 1) sum += __shfl_xor_sync(~0u, sum, o);
    float mu = sum * (1.0f / 64.0f);
    float d0 = v0 - mu, d1 = v1 - mu;
    float vs = d0 * d0 + d1 * d1;
    #pragma unroll
    for (int o = 16; o; o >>= 1) vs += __shfl_xor_sync(~0u, vs, o);
    float inv = rsqrtf(vs * (1.0f / 64.0f) + 1e-5f);
    p[lane]      = d0 * inv * gamma[lane]      + beta[lane];
    p[lane + 32] = d1 * inv * gamma[lane + 32] + beta[lane + 32];
}

// ---------------------------------------------------------------------------
// Flash attention pass: O = softmax(Q K^T / 8) @ V
//   finalPass==0: V := g_k, accumulate ssq of (O - Q) for the eps gate.
//   finalPass==1: V := g_v.
// grid = (SEQ/64, BHD), 256 threads, 64KB dynamic smem.
// Thread (ty,tx) owns rows ty*4+i, cols tx*4+j of each 64x64 tile.
// ---------------------------------------------------------------------------
__global__ __launch_bounds__(256)
void attn_kernel(int finalPass)
{
    extern __shared__ float sm[];
    float* qst = sm;            // [d][r]  (q transposed)
    float* kst = sm + 4096;     // [d][c]  (k transposed)
    float* kv  = sm + 8192;     // [c][n]  (value tile, natural)
    float* pst = sm + 12288;    // [c][r]  (probs transposed)
    __shared__ float red[8];

    const float* Q = g_q;
    const float* K = g_k;
    const float* V = finalPass ? g_v : g_k;
    float*       O = g_nq;

    const int bh = blockIdx.y;
    const int q0 = blockIdx.x * 64;
    const int tid = threadIdx.x;
    const int tx = tid & 15, ty = tid >> 4;

    const int lr = tid >> 2;            // 0..63
    const int lc = (tid & 3) * 4;       // 0,4,8,12 (+16j)

    const float* qb = Q + ((size_t)bh * SEQ + q0) * DK;
    const float* kb = K + (size_t)bh * SEQ * DK;
    const float* vb = V + (size_t)bh * SEQ * DK;

    // load Q tile transposed
    #pragma unroll
    for (int j = 0; j < 4; j++) {
        int d = lc + 16 * j;
        float4 v4 = *(const float4*)(qb + (size_t)lr * DK + d);
        qst[(d + 0) * 64 + lr] = v4.x;
        qst[(d + 1) * 64 + lr] = v4.y;
        qst[(d + 2) * 64 + lr] = v4.z;
        qst[(d + 3) * 64 + lr] = v4.w;
    }

    float m[4], l[4], o[4][4];
    #pragma unroll
    for (int i = 0; i < 4; i++) {
        m[i] = -1e30f; l[i] = 0.0f;
        #pragma unroll
        for (int j = 0; j < 4; j++) o[i][j] = 0.0f;
    }

    for (int kt = 0; kt < SEQ / 64; kt++) {
        __syncthreads();  // protect smem reuse (also orders qst writes at kt=0)
        // load K tile transposed + V tile natural
        #pragma unroll
        for (int j = 0; j < 4; j++) {
            int d = lc + 16 * j;
            float4 v4 = *(const float4*)(kb + (size_t)(kt * 64 + lr) * DK + d);
            kst[(d + 0) * 64 + lr] = v4.x;
            kst[(d + 1) * 64 + lr] = v4.y;
            kst[(d + 2) * 64 + lr] = v4.z;
            kst[(d + 3) * 64 + lr] = v4.w;
            float4 vv = *(const float4*)(vb + (size_t)(kt * 64 + lr) * DK + d);
            *(float4*)&kv[lr * 64 + d] = vv;
        }
        __syncthreads();

        // scores s = (Q K^T) for this tile
        float s[4][4] = {};
        #pragma unroll 16
        for (int kk = 0; kk < 64; kk++) {
            float4 a4 = *(float4*)&qst[kk * 64 + ty * 4];
            float4 b4 = *(float4*)&kst[kk * 64 + tx * 4];
            float aa[4] = {a4.x, a4.y, a4.z, a4.w};
            float bb[4] = {b4.x, b4.y, b4.z, b4.w};
            #pragma unroll
            for (int i = 0; i < 4; i++)
                #pragma unroll
                for (int j = 0; j < 4; j++)
                    s[i][j] += aa[i] * bb[j];
        }
        #pragma unroll
        for (int i = 0; i < 4; i++)
            #pragma unroll
            for (int j = 0; j < 4; j++)
                s[i][j] *= 0.125f;   // 1/sqrt(64)

        // online softmax (row reduce across the 16 tx lanes of this ty group)
        #pragma unroll
        for (int i = 0; i < 4; i++) {
            float mx = fmaxf(fmaxf(s[i][0], s[i][1]), fmaxf(s[i][2], s[i][3]));
            #pragma unroll
            for (int off = 8; off; off >>= 1)
                mx = fmaxf(mx, __shfl_xor_sync(~0u, mx, off));
            float mnew = fmaxf(m[i], mx);
            float corr = __expf(m[i] - mnew);
            float rs = 0.0f;
            #pragma unroll
            for (int j = 0; j < 4; j++) {
                float pv = __expf(s[i][j] - mnew);
                s[i][j] = pv;
                rs += pv;
            }
            #pragma unroll
            for (int off = 8; off; off >>= 1)
                rs += __shfl_xor_sync(~0u, rs, off);
            l[i] = l[i] * corr + rs;
            m[i] = mnew;
            #pragma unroll
            for (int j = 0; j < 4; j++) {
                o[i][j] *= corr;
                pst[(tx * 4 + j) * 64 + ty * 4 + i] = s[i][j];
            }
        }
        __syncwarp();  // pst produced/consumed within the same warp half

        // O += P @ V
        #pragma unroll 16
        for (int c = 0; c < 64; c++) {
            float4 a4 = *(float4*)&pst[c * 64 + ty * 4];
            float4 b4 = *(float4*)&kv[c * 64 + tx * 4];
            float aa[4] = {a4.x, a4.y, a4.z, a4.w};
            float bb[4] = {b4.x, b4.y, b4.z, b4.w};
            #pragma unroll
            for (int i = 0; i < 4; i++)
                #pragma unroll
                for (int j = 0; j < 4; j++)
                    o[i][j] += aa[i] * bb[j];
        }
    }

    // normalize + store (+ diff accumulation for the eps gate)
    float* ob = O + ((size_t)bh * SEQ + q0) * DK;
    float local = 0.0f;
    #pragma unroll
    for (int i = 0; i < 4; i++) {
        float linv = 1.0f / l[i];
        float4 v4;
        v4.x = o[i][0] * linv; v4.y = o[i][1] * linv;
        v4.z = o[i][2] * linv; v4.w = o[i][3] * linv;
        int r = ty * 4 + i;
        *(float4*)&ob[r * 64 + tx * 4] = v4;
        if (!finalPass) {
            float4 qv = *(const float4*)&qb[r * 64 + tx * 4];
            float d0 = v4.x - qv.x, d1 = v4.y - qv.y;
            float d2 = v4.z - qv.z, d3 = v4.w - qv.w;
            local += d0 * d0 + d1 * d1 + d2 * d2 + d3 * d3;
        }
    }
    if (!finalPass) {
        #pragma unroll
        for (int off = 16; off; off >>= 1)
            local += __shfl_xor_sync(~0u, local, off);
        if ((tid & 31) == 0) red[tid >> 5] = local;
        __syncthreads();
        if (tid == 0) {
            float t = 0.0f;
            #pragma unroll
            for (int i = 0; i < 8; i++) t += red[i];
            atomicAdd(&g_ssq, t);
        }
    }
}

// ---------------------------------------------------------------------------
__global__ void reset_ssq_kernel() { g_ssq = 0.0f; }

// eps gate: q <- new_q iff ||new_q - q||_F > 1e-4  (i.e. ssq > 1e-8)
__global__ __launch_bounds__(256)
void gate_kernel()
{
    bool upd = g_ssq > 1e-8f;
    int idx = blockIdx.x * blockDim.x + threadIdx.x;
    if (upd) ((float4*)g_q)[idx] = ((const float4*)g_nq)[idx];
}

// ---------------------------------------------------------------------------
// Output projection: C = concat_heads(attn_out) @ Wo + bo
// attn_out lives in g_nq with (B,H,S,64) layout; gathered on load.
// grid = (TOKENS/64, DMODEL/64)
// ---------------------------------------------------------------------------
__global__ __launch_bounds__(256)
void out_gemm(const float* __restrict__ Wo, const float* __restrict__ bo,
              float* __restrict__ C)
{
    __shared__ float As[16][64];
    __shared__ float Bs[16][64];

    const int n0   = blockIdx.y * 64;
    const int row0 = blockIdx.x * 64;
    const int tid = threadIdx.x;
    const int tx = tid & 15, ty = tid >> 4;

    const int ar = tid >> 2;
    const int ac = (tid & 3) * 4;
    const int br = tid >> 4;
    const int bc = (tid & 15) * 4;

    const int t = row0 + ar;
    const int b = t >> 10, s = t & 1023;

    float acc[4][4] = {};

    for (int k0 = 0; k0 < DMODEL; k0 += 16) {
        int kk = k0 + ac;
        int h = kk >> 6, d = kk & 63;
        float4 av = *(const float4*)(g_nq + (((size_t)b * NHEADS + h) * SEQ + s) * DK + d);
        As[ac + 0][ar] = av.x; As[ac + 1][ar] = av.y;
        As[ac + 2][ar] = av.z; As[ac + 3][ar] = av.w;
        float4 b4 = *(const float4*)(Wo + (size_t)(k0 + br) * DMODEL + n0 + bc);
        *(float4*)&Bs[br][bc] = b4;
        __syncthreads();
        #pragma unroll
        for (int kki = 0; kki < 16; kki++) {
            float4 a4 = *(float4*)&As[kki][ty * 4];
            float4 bb4 = *(float4*)&Bs[kki][tx * 4];
            float aa[4] = {a4.x, a4.y, a4.z, a4.w};
            float bb[4] = {bb4.x, bb4.y, bb4.z, bb4.w};
            #pragma unroll
            for (int i = 0; i < 4; i++)
                #pragma unroll
                for (int j = 0; j < 4; j++)
                    acc[i][j] += aa[i] * bb[j];
        }
        __syncthreads();
    }

    float4 bia = *(const float4*)(bo + n0 + tx * 4);
    #pragma unroll
    for (int i = 0; i < 4; i++) {
        int tr = row0 + ty * 4 + i;
        float4 v4;
        v4.x = acc[i][0] + bia.x; v4.y = acc[i][1] + bia.y;
        v4.z = acc[i][2] + bia.z; v4.w = acc[i][3] + bia.w;
        *(float4*)&C[(size_t)tr * DMODEL + n0 + tx * 4] = v4;
    }
}

// ---------------------------------------------------------------------------
extern "C" void kernel_launch(void* const* d_in, const int* in_sizes, int n_in,
                              void* d_out, int out_size)
{
    const float* x     = (const float*)d_in[0];
    const float* Wq    = (const float*)d_in[1];
    const float* bq    = (const float*)d_in[2];
    const float* Wk    = (const float*)d_in[3];
    const float* bk    = (const float*)d_in[4];
    const float* Wv    = (const float*)d_in[5];
    const float* bv    = (const float*)d_in[6];
    const float* Wo    = (const float*)d_in[7];
    const float* bo    = (const float*)d_in[8];
    const float* gamma = (const float*)d_in[9];
    const float* beta  = (const float*)d_in[10];
    float* out = (float*)d_out;

    cudaFuncSetAttribute(attn_kernel,
                         cudaFuncAttributeMaxDynamicSharedMemorySize, 65536);

    // 1. QKV projections into (B,H,S,64)
    qkv_gemm<<<dim3(TOKENS / 64, 24), 256>>>(x, Wq, bq, Wk, bk, Wv, bv);
    // 2. LayerNorm on q and k
    ln_kernel<<<(2 * BHD * SEQ) / 8, 256>>>(gamma, beta);
    // 3. Hopfield update iterations with exact eps gating
    for (int it = 0; it < 3; it++) {
        reset_ssq_kernel<<<1, 1>>>();
        attn_kernel<<<dim3(SEQ / 64, BHD), 256, 65536>>>(0);
        gate_kernel<<<QKV_ELEMS / 4 / 256, 256>>>();
    }
    // 4. Final retrieval with values
    attn_kernel<<<dim3(SEQ / 64, BHD), 256, 65536>>>(1);
    // 5. Output projection
    out_gemm<<<dim3(TOKENS / 64, DMODEL / 64), 256>>>(Wo, bo, out);
}

// round 3
// speedup vs baseline: 1.1596x; 1.1596x over previous
#include <cuda_runtime.h>

#define NHEADS   8
#define DK       64
#define SEQ      1024
#define BATCH    8
#define DMODEL   512
#define BHD      (BATCH*NHEADS)          // 64
#define TOKENS   (BATCH*SEQ)             // 8192
#define QKV_ELEMS (BHD*SEQ*DK)           // 4194304
#define KVPAD    68

typedef unsigned long long u64;

// ---------------- scratch (device globals; no allocation allowed) ----------
__device__ float g_q[QKV_ELEMS];
__device__ float g_k[QKV_ELEMS];
__device__ float g_v[QKV_ELEMS];
__device__ float g_nq[QKV_ELEMS];
__device__ float g_ssq;

// ---------------- packed f32x2 helpers -------------------------------------
__device__ __forceinline__ u64 pack2(float lo, float hi) {
    u64 r; asm("mov.b64 %0, {%1, %2};" : "=l"(r) : "f"(lo), "f"(hi)); return r;
}
__device__ __forceinline__ void unpack2(u64 v, float& lo, float& hi) {
    asm("mov.b64 {%0, %1}, %2;" : "=f"(lo), "=f"(hi) : "l"(v));
}
__device__ __forceinline__ void fma2(u64& d, u64 a, u64 b) {
    asm("fma.rn.f32x2 %0, %1, %2, %0;" : "+l"(d) : "l"(a), "l"(b));
}
__device__ __forceinline__ u64 mul2(u64 a, u64 b) {
    u64 r; asm("mul.rn.f32x2 %0, %1, %2;" : "=l"(r) : "l"(a), "l"(b)); return r;
}

// ---------------------------------------------------------------------------
// QKV projection + fused LayerNorm (for q,k). 128x64 tile, 8x8 microtile,
// f32x2 packed FMA. grid = (TOKENS/128, 24): blockIdx.y = mat*8 + head.
// ---------------------------------------------------------------------------
__global__ __launch_bounds__(128)
void qkv_gemm(const float* __restrict__ x,
              const float* __restrict__ Wq, const float* __restrict__ bq,
              const float* __restrict__ Wk, const float* __restrict__ bk,
              const float* __restrict__ Wv, const float* __restrict__ bv,
              const float* __restrict__ gamma, const float* __restrict__ beta)
{
    __shared__ float As[32 * 128];   // [k][m] transposed
    __shared__ float Bs[32 * 64];    // [k][n]

    const int mat  = blockIdx.y >> 3;
    const int head = blockIdx.y & 7;
    const int row0 = blockIdx.x * 128;

    const float* W    = (mat == 0) ? Wq : (mat == 1) ? Wk : Wv;
    const float* bias = (mat == 0) ? bq : (mat == 1) ? bk : bv;
    float*       out  = (mat == 0) ? g_q : (mat == 1) ? g_k : g_v;

    const int tid = threadIdx.x;
    const int tx = tid & 7, ty = tid >> 3;

    u64 acc2[4][8];
    #pragma unroll
    for (int ip = 0; ip < 4; ip++)
        #pragma unroll
        for (int j = 0; j < 8; j++) acc2[ip][j] = 0ull;

    for (int k0 = 0; k0 < DMODEL; k0 += 32) {
        __syncthreads();
        // A chunk, transposed: thread owns row (row0+tid)
        {
            const float4* xr = (const float4*)(x + (size_t)(row0 + tid) * DMODEL + k0);
            #pragma unroll
            for (int rep = 0; rep < 8; rep++) {
                float4 v = xr[rep];
                int d = rep * 4;
                As[(d + 0) * 128 + tid] = v.x;
                As[(d + 1) * 128 + tid] = v.y;
                As[(d + 2) * 128 + tid] = v.z;
                As[(d + 3) * 128 + tid] = v.w;
            }
        }
        // B chunk natural
        #pragma unroll
        for (int rep = 0; rep < 4; rep++) {
            int idx = tid + 128 * rep;
            int kb = idx >> 4, nc = (idx & 15) * 4;
            *(float4*)&Bs[kb * 64 + nc] =
                *(const float4*)(W + (size_t)(k0 + kb) * DMODEL + head * 64 + nc);
        }
        __syncthreads();

        #pragma unroll 8
        for (int kk = 0; kk < 32; kk++) {
            ulonglong2 a01 = *(const ulonglong2*)&As[kk * 128 + ty * 8];
            ulonglong2 a23 = *(const ulonglong2*)&As[kk * 128 + ty * 8 + 4];
            u64 ap[4] = {a01.x, a01.y, a23.x, a23.y};
            float4 b0 = *(const float4*)&Bs[kk * 64 + tx * 8];
            float4 b1 = *(const float4*)&Bs[kk * 64 + tx * 8 + 4];
            float bf[8] = {b0.x, b0.y, b0.z, b0.w, b1.x, b1.y, b1.z, b1.w};
            #pragma unroll
            for (int j = 0; j < 8; j++) {
                u64 bb = pack2(bf[j], bf[j]);
                #pragma unroll
                for (int ip = 0; ip < 4; ip++) fma2(acc2[ip][j], ap[ip], bb);
            }
        }
    }

    // epilogue: unpack, bias, (LN for q/k), store to (B,H,S,64)
    float v[8][8];
    #pragma unroll
    for (int ip = 0; ip < 4; ip++)
        #pragma unroll
        for (int j = 0; j < 8; j++)
            unpack2(acc2[ip][j], v[2 * ip][j], v[2 * ip + 1][j]);

    float bi[8], ga[8], be[8];
    #pragma unroll
    for (int j = 0; j < 8; j++) {
        bi[j] = bias[head * 64 + tx * 8 + j];
        ga[j] = gamma[tx * 8 + j];
        be[j] = beta[tx * 8 + j];
    }
    #pragma unroll
    for (int i = 0; i < 8; i++)
        #pragma unroll
        for (int j = 0; j < 8; j++) v[i][j] += bi[j];

    if (mat < 2) {
        #pragma unroll
        for (int i = 0; i < 8; i++) {
            float sum = 0.f;
            #pragma unroll
            for (int j = 0; j < 8; j++) sum += v[i][j];
            sum += __shfl_xor_sync(~0u, sum, 1);
            sum += __shfl_xor_sync(~0u, sum, 2);
            sum += __shfl_xor_sync(~0u, sum, 4);
            float mu = sum * (1.0f / 64.0f);
            float ss = 0.f;
            #pragma unroll
            for (int j = 0; j < 8; j++) {
                v[i][j] -= mu;
                ss += v[i][j] * v[i][j];
            }
            ss += __shfl_xor_sync(~0u, ss, 1);
            ss += __shfl_xor_sync(~0u, ss, 2);
            ss += __shfl_xor_sync(~0u, ss, 4);
            float inv = rsqrtf(ss * (1.0f / 64.0f) + 1e-5f);
            #pragma unroll
            for (int j = 0; j < 8; j++) v[i][j] = v[i][j] * inv * ga[j] + be[j];
        }
    }

    #pragma unroll
    for (int i = 0; i < 8; i++) {
        int t = row0 + ty * 8 + i;
        int b = t >> 10, s = t & 1023;
        float* orow = out + (((size_t)b * NHEADS + head) * SEQ + s) * DK + tx * 8;
        *(float4*)orow       = make_float4(v[i][0], v[i][1], v[i][2], v[i][3]);
        *(float4*)(orow + 4) = make_float4(v[i][4], v[i][5], v[i][6], v[i][7]);
    }
}

// ---------------------------------------------------------------------------
// Flash attention pass: O = softmax(Q K^T / 8) @ V
// Q tile 128, K tile 64, 128 threads, 8x8 microtile, f32x2 FMA.
//   finalPass==0: V := g_k, accumulate ssq of (O - Q).
//   finalPass==1: V := g_v.
// grid = (SEQ/128, BHD). Dynamic smem = 99328 B.
// ---------------------------------------------------------------------------
__global__ __launch_bounds__(128, 2)
void attn_kernel(int finalPass)
{
    extern __shared__ float sm[];
    float* qst = sm;                        // [64][128] Q^T
    float* kst = sm + 8192;                 // [64][64]  K^T
    float* kv  = sm + 12288;                // [64][KVPAD] V natural (padded)
    float* pst = sm + 12288 + 64 * KVPAD;   // [64][128] P^T, xor-swizzled
    __shared__ float red[4];

    const float* Q = g_q;
    const float* K = g_k;
    const float* V = finalPass ? g_v : g_k;

    const int bh = blockIdx.y;
    const int q0 = blockIdx.x * 128;
    const int tid = threadIdx.x;
    const int tx = tid & 7, ty = tid >> 3;

    const float* qb = Q + ((size_t)bh * SEQ + q0) * DK;
    const float* kb = K + (size_t)bh * SEQ * DK;
    const float* vb = V + (size_t)bh * SEQ * DK;

    // Q tile transposed (thread = one row, conflict-free scalar STS)
    {
        const float4* qrow = (const float4*)(qb + (size_t)tid * DK);
        #pragma unroll
        for (int rep = 0; rep < 16; rep++) {
            float4 v = qrow[rep];
            int d = rep * 4;
            qst[(d + 0) * 128 + tid] = v.x;
            qst[(d + 1) * 128 + tid] = v.y;
            qst[(d + 2) * 128 + tid] = v.z;
            qst[(d + 3) * 128 + tid] = v.w;
        }
    }

    float m[8], l[8];
    u64 o2[4][8];
    #pragma unroll
    for (int i = 0; i < 8; i++) { m[i] = -1e30f; l[i] = 0.f; }
    #pragma unroll
    for (int ip = 0; ip < 4; ip++)
        #pragma unroll
        for (int j = 0; j < 8; j++) o2[ip][j] = 0ull;

    const int kr = tid & 63, khalf = tid >> 6;

    for (int kt = 0; kt < SEQ / 64; kt++) {
        __syncthreads();
        // load K^T and V tiles
        {
            const float* krow = kb + (size_t)(kt * 64 + kr) * DK;
            const float* vrow = vb + (size_t)(kt * 64 + kr) * DK;
            #pragma unroll
            for (int rep = 0; rep < 8; rep++) {
                int d = khalf * 32 + rep * 4;
                float4 v = *(const float4*)(krow + d);
                kst[(d + 0) * 64 + kr] = v.x;
                kst[(d + 1) * 64 + kr] = v.y;
                kst[(d + 2) * 64 + kr] = v.z;
                kst[(d + 3) * 64 + kr] = v.w;
                float4 w = *(const float4*)(vrow + d);
                *(float4*)&kv[kr * KVPAD + d] = w;
            }
        }
        __syncthreads();

        // ---- scores S = Q K^T ----
        u64 s2[4][8];
        #pragma unroll
        for (int ip = 0; ip < 4; ip++)
            #pragma unroll
            for (int j = 0; j < 8; j++) s2[ip][j] = 0ull;

        #pragma unroll 8
        for (int kk = 0; kk < 64; kk++) {
            ulonglong2 a01 = *(const ulonglong2*)&qst[kk * 128 + ty * 8];
            ulonglong2 a23 = *(const ulonglong2*)&qst[kk * 128 + ty * 8 + 4];
            u64 ap[4] = {a01.x, a01.y, a23.x, a23.y};
            float4 b0 = *(const float4*)&kst[kk * 64 + tx * 8];
            float4 b1 = *(const float4*)&kst[kk * 64 + tx * 8 + 4];
            float bf[8] = {b0.x, b0.y, b0.z, b0.w, b1.x, b1.y, b1.z, b1.w};
            #pragma unroll
            for (int j = 0; j < 8; j++) {
                u64 bb = pack2(bf[j], bf[j]);
                #pragma unroll
                for (int ip = 0; ip < 4; ip++) fma2(s2[ip][j], ap[ip], bb);
            }
        }

        // ---- online softmax ----
        float s[8][8];
        #pragma unroll
        for (int ip = 0; ip < 4; ip++)
            #pragma unroll
            for (int j = 0; j < 8; j++) {
                float lo, hi; unpack2(s2[ip][j], lo, hi);
                s[2 * ip][j]     = lo * 0.125f;
                s[2 * ip + 1][j] = hi * 0.125f;
            }
        float corrv[8];
        #pragma unroll
        for (int i = 0; i < 8; i++) {
            float mx = s[i][0];
            #pragma unroll
            for (int j = 1; j < 8; j++) mx = fmaxf(mx, s[i][j]);
            mx = fmaxf(mx, __shfl_xor_sync(~0u, mx, 1));
            mx = fmaxf(mx, __shfl_xor_sync(~0u, mx, 2));
            mx = fmaxf(mx, __shfl_xor_sync(~0u, mx, 4));
            float mnew = fmaxf(m[i], mx);
            float corr = __expf(m[i] - mnew);
            float rs = 0.f;
            #pragma unroll
            for (int j = 0; j < 8; j++) {
                float p = __expf(s[i][j] - mnew);
                s[i][j] = p;
                rs += p;
            }
            rs += __shfl_xor_sync(~0u, rs, 1);
            rs += __shfl_xor_sync(~0u, rs, 2);
            rs += __shfl_xor_sync(~0u, rs, 4);
            l[i] = l[i] * corr + rs;
            m[i] = mnew;
            corrv[i] = corr;
        }
        #pragma unroll
        for (int ip = 0; ip < 4; ip++) {
            u64 c2 = pack2(corrv[2 * ip], corrv[2 * ip + 1]);
            #pragma unroll
            for (int j = 0; j < 8; j++) o2[ip][j] = mul2(o2[ip][j], c2);
        }

        // ---- store P^T (xor-swizzled rows) ----
        {
            int swz = tx << 4;
            #pragma unroll
            for (int j = 0; j < 8; j++) {
                int c = tx * 8 + j;
                float* dst = &pst[c * 128 + ((ty * 8) ^ swz)];
                *(float4*)dst       = make_float4(s[0][j], s[1][j], s[2][j], s[3][j]);
                *(float4*)(dst + 4) = make_float4(s[4][j], s[5][j], s[6][j], s[7][j]);
            }
        }
        __syncwarp();   // P produced & consumed within the same warp

        // ---- O += P @ V ----
        #pragma unroll 8
        for (int c = 0; c < 64; c++) {
            int sw = (c >> 3) << 4;
            const float* pr = &pst[c * 128 + ((ty * 8) ^ sw)];
            ulonglong2 a01 = *(const ulonglong2*)pr;
            ulonglong2 a23 = *(const ulonglong2*)(pr + 4);
            u64 ap[4] = {a01.x, a01.y, a23.x, a23.y};
            float4 b0 = *(const float4*)&kv[c * KVPAD + tx * 8];
            float4 b1 = *(const float4*)&kv[c * KVPAD + tx * 8 + 4];
            float bf[8] = {b0.x, b0.y, b0.z, b0.w, b1.x, b1.y, b1.z, b1.w};
            #pragma unroll
            for (int j = 0; j < 8; j++) {
                u64 bb = pack2(bf[j], bf[j]);
                #pragma unroll
                for (int ip = 0; ip < 4; ip++) fma2(o2[ip][j], ap[ip], bb);
            }
        }
    }

    // ---- normalize + store (+ ssq for eps gate) ----
    float o[8][8];
    #pragma unroll
    for (int ip = 0; ip < 4; ip++)
        #pragma unroll
        for (int j = 0; j < 8; j++)
            unpack2(o2[ip][j], o[2 * ip][j], o[2 * ip + 1][j]);

    float* ob = g_nq + ((size_t)bh * SEQ + q0) * DK;
    float local = 0.f;
    #pragma unroll
    for (int i = 0; i < 8; i++) {
        float linv = 1.0f / l[i];
        #pragma unroll
        for (int j = 0; j < 8; j++) o[i][j] *= linv;
        int r = ty * 8 + i;
        float* dst = ob + (size_t)r * DK + tx * 8;
        *(float4*)dst       = make_float4(o[i][0], o[i][1], o[i][2], o[i][3]);
        *(float4*)(dst + 4) = make_float4(o[i][4], o[i][5], o[i][6], o[i][7]);
        if (!finalPass) {
            const float* qs = qb + (size_t)r * DK + tx * 8;
            float4 q0v = *(const float4*)qs;
            float4 q1v = *(const float4*)(qs + 4);
            float qf[8] = {q0v.x, q0v.y, q0v.z, q0v.w, q1v.x, q1v.y, q1v.z, q1v.w};
            #pragma unroll
            for (int j = 0; j < 8; j++) {
                float d = o[i][j] - qf[j];
                local += d * d;
            }
        }
    }
    if (!finalPass) {
        #pragma unroll
        for (int off = 16; off; off >>= 1)
            local += __shfl_xor_sync(~0u, local, off);
        if ((tid & 31) == 0) red[tid >> 5] = local;
        __syncthreads();
        if (tid == 0)
            atomicAdd(&g_ssq, red[0] + red[1] + red[2] + red[3]);
    }
}

// ---------------------------------------------------------------------------
__global__ void reset_ssq_kernel() { g_ssq = 0.0f; }

__global__ __launch_bounds__(256)
void gate_kernel()
{
    bool upd = g_ssq > 1e-8f;   // ||diff|| > 1e-4
    int idx = blockIdx.x * blockDim.x + threadIdx.x;
    if (upd) ((float4*)g_q)[idx] = ((const float4*)g_nq)[idx];
}

// ---------------------------------------------------------------------------
// Output projection: C = concat_heads(g_nq) @ Wo + bo. 128x64 tiles.
// grid = (TOKENS/128, DMODEL/64)
// ---------------------------------------------------------------------------
__global__ __launch_bounds__(128)
void out_gemm(const float* __restrict__ Wo, const float* __restrict__ bo,
              float* __restrict__ C)
{
    __shared__ float As[32 * 128];
    __shared__ float Bs[32 * 64];

    const int n0   = blockIdx.y * 64;
    const int row0 = blockIdx.x * 128;
    const int tid = threadIdx.x;
    const int tx = tid & 7, ty = tid >> 3;

    const int t = row0 + tid;
    const int b = t >> 10, sdx = t & 1023;

    u64 acc2[4][8];
    #pragma unroll
    for (int ip = 0; ip < 4; ip++)
        #pragma unroll
        for (int j = 0; j < 8; j++) acc2[ip][j] = 0ull;

    for (int k0 = 0; k0 < DMODEL; k0 += 32) {
        __syncthreads();
        {
            int h = k0 >> 6, dbase = k0 & 63;
            const float4* ar = (const float4*)(g_nq +
                (((size_t)b * NHEADS + h) * SEQ + sdx) * DK + dbase);
            #pragma unroll
            for (int rep = 0; rep < 8; rep++) {
                float4 v = ar[rep];
                int d = rep * 4;
                As[(d + 0) * 128 + tid] = v.x;
                As[(d + 1) * 128 + tid] = v.y;
                As[(d + 2) * 128 + tid] = v.z;
                As[(d + 3) * 128 + tid] = v.w;
            }
        }
        #pragma unroll
        for (int rep = 0; rep < 4; rep++) {
            int idx = tid + 128 * rep;
            int kb = idx >> 4, nc = (idx & 15) * 4;
            *(float4*)&Bs[kb * 64 + nc] =
                *(const float4*)(Wo + (size_t)(k0 + kb) * DMODEL + n0 + nc);
        }
        __syncthreads();

        #pragma unroll 8
        for (int kk = 0; kk < 32; kk++) {
            ulonglong2 a01 = *(const ulonglong2*)&As[kk * 128 + ty * 8];
            ulonglong2 a23 = *(const ulonglong2*)&As[kk * 128 + ty * 8 + 4];
            u64 ap[4] = {a01.x, a01.y, a23.x, a23.y};
            float4 b0 = *(const float4*)&Bs[kk * 64 + tx * 8];
            float4 b1 = *(const float4*)&Bs[kk * 64 + tx * 8 + 4];
            float bf[8] = {b0.x, b0.y, b0.z, b0.w, b1.x, b1.y, b1.z, b1.w};
            #pragma unroll
            for (int j = 0; j < 8; j++) {
                u64 bb = pack2(bf[j], bf[j]);
                #pragma unroll
                for (int ip = 0; ip < 4; ip++) fma2(acc2[ip][j], ap[ip], bb);
            }
        }
    }

    float v[8][8];
    #pragma unroll
    for (int ip = 0; ip < 4; ip++)
        #pragma unroll
        for (int j = 0; j < 8; j++)
            unpack2(acc2[ip][j], v[2 * ip][j], v[2 * ip + 1][j]);

    float bi[8];
    #pragma unroll
    for (int j = 0; j < 8; j++) bi[j] = bo[n0 + tx * 8 + j];

    #pragma unroll
    for (int i = 0; i < 8; i++) {
        int tr = row0 + ty * 8 + i;
        float* dst = C + (size_t)tr * DMODEL + n0 + tx * 8;
        *(float4*)dst = make_float4(v[i][0] + bi[0], v[i][1] + bi[1],
                                    v[i][2] + bi[2], v[i][3] + bi[3]);
        *(float4*)(dst + 4) = make_float4(v[i][4] + bi[4], v[i][5] + bi[5],
                                          v[i][6] + bi[6], v[i][7] + bi[7]);
    }
}

// ---------------------------------------------------------------------------
extern "C" void kernel_launch(void* const* d_in, const int* in_sizes, int n_in,
                              void* d_out, int out_size)
{
    const float* x     = (const float*)d_in[0];
    const float* Wq    = (const float*)d_in[1];
    const float* bq    = (const float*)d_in[2];
    const float* Wk    = (const float*)d_in[3];
    const float* bk    = (const float*)d_in[4];
    const float* Wv    = (const float*)d_in[5];
    const float* bv    = (const float*)d_in[6];
    const float* Wo    = (const float*)d_in[7];
    const float* bo    = (const float*)d_in[8];
    const float* gamma = (const float*)d_in[9];
    const float* beta  = (const float*)d_in[10];
    float* out = (float*)d_out;

    static int smem_set = 0;
    if (!smem_set) {
        cudaFuncSetAttribute(attn_kernel,
                             cudaFuncAttributeMaxDynamicSharedMemorySize, 99328);
        smem_set = 1;
    }

    // 1. QKV projections (+ fused LayerNorm for q,k) into (B,H,S,64)
    qkv_gemm<<<dim3(TOKENS / 128, 24), 128>>>(x, Wq, bq, Wk, bk, Wv, bv,
                                              gamma, beta);
    // 2. Hopfield update iterations with exact eps gating
    for (int it = 0; it < 3; it++) {
        reset_ssq_kernel<<<1, 1>>>();
        attn_kernel<<<dim3(SEQ / 128, BHD), 128, 99328>>>(0);
        gate_kernel<<<QKV_ELEMS / 4 / 256, 256>>>();
    }
    // 3. Final retrieval with values
    attn_kernel<<<dim3(SEQ / 128, BHD), 128, 99328>>>(1);
    // 4. Output projection
    out_gemm<<<dim3(TOKENS / 128, DMODEL / 64), 128>>>(Wo, bo, out);
}

// round 8
// speedup vs baseline: 2.3732x; 2.0466x over previous
#include <cuda_runtime.h>
#include <cuda_bf16.h>
#include <cstdint>

#define NHEADS   8
#define DK       64
#define SEQ      1024
#define BATCH    8
#define DMODEL   512
#define BHD      (BATCH*NHEADS)          // 64
#define TOKENS   (BATCH*SEQ)             // 8192
#define QKV_ELEMS (BHD*SEQ*DK)           // 4194304

typedef unsigned long long u64;

// ---------------- scratch (device globals; no allocation allowed) ----------
__device__ float g_q[QKV_ELEMS];
__device__ float g_k[QKV_ELEMS];
__device__ float g_v[QKV_ELEMS];
__device__ float g_nq[QKV_ELEMS];
__device__ float g_ssq;

// bf16 hi/lo splits of K (K-major), K^T and V^T (d-major), built once.
__device__ __align__(256) __nv_bfloat16 gk_hi[QKV_ELEMS];
__device__ __align__(256) __nv_bfloat16 gk_lo[QKV_ELEMS];
__device__ __align__(256) __nv_bfloat16 gkt_hi[QKV_ELEMS];
__device__ __align__(256) __nv_bfloat16 gkt_lo[QKV_ELEMS];
__device__ __align__(256) __nv_bfloat16 gvt_hi[QKV_ELEMS];
__device__ __align__(256) __nv_bfloat16 gvt_lo[QKV_ELEMS];

// ---------------- helpers ----------------------------------------------------
__device__ __forceinline__ u64 pack2(float lo, float hi) {
    u64 r; asm("mov.b64 %0, {%1, %2};" : "=l"(r) : "f"(lo), "f"(hi)); return r;
}
__device__ __forceinline__ void unpack2(u64 v, float& lo, float& hi) {
    asm("mov.b64 {%0, %1}, %2;" : "=f"(lo), "=f"(hi) : "l"(v));
}
__device__ __forceinline__ void fma2(u64& d, u64 a, u64 b) {
    asm("fma.rn.f32x2 %0, %1, %2, %0;" : "+l"(d) : "l"(a), "l"(b));
}
__device__ __forceinline__ void hilo(float x, float& h, float& l) {
    h = __bfloat162float(__float2bfloat16(x));
    l = x - h;
}
__device__ __forceinline__ uint32_t bfpack(float a, float b) {
    uint32_t r;
    asm("{ .reg .b16 lo, hi;\n\t"
        "cvt.rn.bf16.f32 lo, %1;\n\t"
        "cvt.rn.bf16.f32 hi, %2;\n\t"
        "mov.b32 %0, {lo, hi}; }"
        : "=r"(r) : "f"(a), "f"(b));
    return r;
}
// m16n8k16 bf16 MMA, f32 accumulate (sm_80 baseline PTX -> HMMA on sm_103a)
__device__ __forceinline__ void mma16816(float c[4], const uint32_t a[4],
                                         uint32_t b0, uint32_t b1) {
    asm volatile(
        "mma.sync.aligned.m16n8k16.row.col.f32.bf16.bf16.f32 "
        "{%0,%1,%2,%3}, {%4,%5,%6,%7}, {%8,%9}, {%0,%1,%2,%3};"
        : "+f"(c[0]), "+f"(c[1]), "+f"(c[2]), "+f"(c[3])
        : "r"(a[0]), "r"(a[1]), "r"(a[2]), "r"(a[3]), "r"(b0), "r"(b1));
}

// ---------------------------------------------------------------------------
// QKV projection + fused LayerNorm (q,k). (R3, passing.)
// ---------------------------------------------------------------------------
__global__ __launch_bounds__(128)
void qkv_gemm(const float* __restrict__ x,
              const float* __restrict__ Wq, const float* __restrict__ bq,
              const float* __restrict__ Wk, const float* __restrict__ bk,
              const float* __restrict__ Wv, const float* __restrict__ bv,
              const float* __restrict__ gamma, const float* __restrict__ beta)
{
    __shared__ float As[32 * 128];
    __shared__ float Bs[32 * 64];

    const int mat  = blockIdx.y >> 3;
    const int head = blockIdx.y & 7;
    const int row0 = blockIdx.x * 128;

    const float* W    = (mat == 0) ? Wq : (mat == 1) ? Wk : Wv;
    const float* bias = (mat == 0) ? bq : (mat == 1) ? bk : bv;
    float*       out  = (mat == 0) ? g_q : (mat == 1) ? g_k : g_v;

    const int tid = threadIdx.x;
    const int tx = tid & 7, ty = tid >> 3;

    u64 acc2[4][8];
    #pragma unroll
    for (int ip = 0; ip < 4; ip++)
        #pragma unroll
        for (int j = 0; j < 8; j++) acc2[ip][j] = 0ull;

    for (int k0 = 0; k0 < DMODEL; k0 += 32) {
        __syncthreads();
        {
            const float4* xr = (const float4*)(x + (size_t)(row0 + tid) * DMODEL + k0);
            #pragma unroll
            for (int rep = 0; rep < 8; rep++) {
                float4 v = xr[rep];
                int d = rep * 4;
                As[(d + 0) * 128 + tid] = v.x;
                As[(d + 1) * 128 + tid] = v.y;
                As[(d + 2) * 128 + tid] = v.z;
                As[(d + 3) * 128 + tid] = v.w;
            }
        }
        #pragma unroll
        for (int rep = 0; rep < 4; rep++) {
            int idx = tid + 128 * rep;
            int kb = idx >> 4, nc = (idx & 15) * 4;
            *(float4*)&Bs[kb * 64 + nc] =
                *(const float4*)(W + (size_t)(k0 + kb) * DMODEL + head * 64 + nc);
        }
        __syncthreads();

        #pragma unroll 8
        for (int kk = 0; kk < 32; kk++) {
            ulonglong2 a01 = *(const ulonglong2*)&As[kk * 128 + ty * 8];
            ulonglong2 a23 = *(const ulonglong2*)&As[kk * 128 + ty * 8 + 4];
            u64 ap[4] = {a01.x, a01.y, a23.x, a23.y};
            float4 b0 = *(const float4*)&Bs[kk * 64 + tx * 8];
            float4 b1 = *(const float4*)&Bs[kk * 64 + tx * 8 + 4];
            float bf[8] = {b0.x, b0.y, b0.z, b0.w, b1.x, b1.y, b1.z, b1.w};
            #pragma unroll
            for (int j = 0; j < 8; j++) {
                u64 bb = pack2(bf[j], bf[j]);
                #pragma unroll
                for (int ip = 0; ip < 4; ip++) fma2(acc2[ip][j], ap[ip], bb);
            }
        }
    }

    float v[8][8];
    #pragma unroll
    for (int ip = 0; ip < 4; ip++)
        #pragma unroll
        for (int j = 0; j < 8; j++)
            unpack2(acc2[ip][j], v[2 * ip][j], v[2 * ip + 1][j]);

    float bi[8], ga[8], be[8];
    #pragma unroll
    for (int j = 0; j < 8; j++) {
        bi[j] = bias[head * 64 + tx * 8 + j];
        ga[j] = gamma[tx * 8 + j];
        be[j] = beta[tx * 8 + j];
    }
    #pragma unroll
    for (int i = 0; i < 8; i++)
        #pragma unroll
        for (int j = 0; j < 8; j++) v[i][j] += bi[j];

    if (mat < 2) {
        #pragma unroll
        for (int i = 0; i < 8; i++) {
            float sum = 0.f;
            #pragma unroll
            for (int j = 0; j < 8; j++) sum += v[i][j];
            sum += __shfl_xor_sync(~0u, sum, 1);
            sum += __shfl_xor_sync(~0u, sum, 2);
            sum += __shfl_xor_sync(~0u, sum, 4);
            float mu = sum * (1.0f / 64.0f);
            float ss = 0.f;
            #pragma unroll
            for (int j = 0; j < 8; j++) {
                v[i][j] -= mu;
                ss += v[i][j] * v[i][j];
            }
            ss += __shfl_xor_sync(~0u, ss, 1);
            ss += __shfl_xor_sync(~0u, ss, 2);
            ss += __shfl_xor_sync(~0u, ss, 4);
            float inv = rsqrtf(ss * (1.0f / 64.0f) + 1e-5f);
            #pragma unroll
            for (int j = 0; j < 8; j++) v[i][j] = v[i][j] * inv * ga[j] + be[j];
        }
    }

    #pragma unroll
    for (int i = 0; i < 8; i++) {
        int t = row0 + ty * 8 + i;
        int b = t >> 10, s = t & 1023;
        float* orow = out + (((size_t)b * NHEADS + head) * SEQ + s) * DK + tx * 8;
        *(float4*)orow       = make_float4(v[i][0], v[i][1], v[i][2], v[i][3]);
        *(float4*)(orow + 4) = make_float4(v[i][4], v[i][5], v[i][6], v[i][7]);
    }
}

// ---------------------------------------------------------------------------
// Prep: split K -> bf16 hi/lo (K-major), and K^T, V^T -> bf16 hi/lo (d-major).
// ---------------------------------------------------------------------------
__global__ __launch_bounds__(256)
void prep_kernel()
{
    __shared__ float ts[64][65];
    const int bh = blockIdx.y;
    const int s0 = blockIdx.x * 64;
    const int tid = threadIdx.x;

    for (int idx = tid; idx < 4096; idx += 256) {
        int r = idx >> 6, d = idx & 63;
        float x = g_k[((size_t)bh * SEQ + s0 + r) * DK + d];
        float h, l; hilo(x, h, l);
        size_t o = ((size_t)bh * SEQ + s0 + r) * DK + d;
        gk_hi[o] = __float2bfloat16(h);
        gk_lo[o] = __float2bfloat16(l);
        ts[r][d] = x;
    }
    __syncthreads();
    for (int idx = tid; idx < 4096; idx += 256) {
        int d = idx >> 6, s = idx & 63;
        float x = ts[s][d];
        float h, l; hilo(x, h, l);
        size_t o = ((size_t)bh * DK + d) * SEQ + s0 + s;
        gkt_hi[o] = __float2bfloat16(h);
        gkt_lo[o] = __float2bfloat16(l);
    }
    __syncthreads();
    for (int idx = tid; idx < 4096; idx += 256) {
        int r = idx >> 6, d = idx & 63;
        ts[r][d] = g_v[((size_t)bh * SEQ + s0 + r) * DK + d];
    }
    __syncthreads();
    for (int idx = tid; idx < 4096; idx += 256) {
        int d = idx >> 6, s = idx & 63;
        float x = ts[s][d];
        float h, l; hilo(x, h, l);
        size_t o = ((size_t)bh * DK + d) * SEQ + s0 + s;
        gvt_hi[o] = __float2bfloat16(h);
        gvt_lo[o] = __float2bfloat16(l);
    }
}

// ---------------------------------------------------------------------------
// Attention via mma.sync (legacy HMMA tensor path — baseline sm_80 PTX).
// O = softmax(Q K^T / 8) @ Vals, Vals = K (pass 0-2, accumulating ssq) or V.
// grid = (SEQ/128, BHD), 256 threads (8 warps x 16 q-rows), static smem 36.9KB.
// bf16 hi/lo split: 3 MMA products per GEMM (~1e-4 accuracy).
// Fixed softmax max = 8 (LayerNorm => |score| <= 8): no online rescaling,
// P stays in registers (C-fragment layout == A-fragment layout identity).
// ---------------------------------------------------------------------------
#define KSTR 72   // smem key/d row stride in bf16 (144 B -> conflict-free frags)

__global__ __launch_bounds__(256)
void attn_mma(int finalPass)
{
    __shared__ __align__(16) __nv_bfloat16 s_khi[64 * KSTR];
    __shared__ __align__(16) __nv_bfloat16 s_klo[64 * KSTR];
    __shared__ __align__(16) __nv_bfloat16 s_vhi[64 * KSTR];
    __shared__ __align__(16) __nv_bfloat16 s_vlo[64 * KSTR];

    const int tid  = threadIdx.x;
    const int warp = tid >> 5;
    const int lane = tid & 31;
    const int g = lane >> 2;         // fragment group 0..7
    const int t = lane & 3;          // thread-in-group 0..3
    const int bh = blockIdx.y;
    const int q0 = blockIdx.x * 128;
    const int m0 = warp * 16;        // warp's 16 q-rows

    const float* qb = g_q + ((size_t)bh * SEQ + q0) * DK;

    // ---- Q fragments (hi/lo), loaded straight from gmem ----
    // a0={r g,c 2t..}, a1={r g+8,c 2t..}, a2={r g,c 2t+8..}, a3={r g+8,c 2t+8..}
    uint32_t qh[4][4], ql[4][4];
    {
        const float* r0p = qb + (size_t)(m0 + g) * DK;
        const float* r1p = qb + (size_t)(m0 + g + 8) * DK;
        #pragma unroll
        for (int kt = 0; kt < 4; kt++) {
            float2 v00 = *(const float2*)(r0p + 16 * kt + 2 * t);
            float2 v10 = *(const float2*)(r1p + 16 * kt + 2 * t);
            float2 v01 = *(const float2*)(r0p + 16 * kt + 2 * t + 8);
            float2 v11 = *(const float2*)(r1p + 16 * kt + 2 * t + 8);
            float h0, l0, h1, l1;
            hilo(v00.x, h0, l0); hilo(v00.y, h1, l1);
            qh[kt][0] = bfpack(h0, h1); ql[kt][0] = bfpack(l0, l1);
            hilo(v10.x, h0, l0); hilo(v10.y, h1, l1);
            qh[kt][1] = bfpack(h0, h1); ql[kt][1] = bfpack(l0, l1);
            hilo(v01.x, h0, l0); hilo(v01.y, h1, l1);
            qh[kt][2] = bfpack(h0, h1); ql[kt][2] = bfpack(l0, l1);
            hilo(v11.x, h0, l0); hilo(v11.y, h1, l1);
            qh[kt][3] = bfpack(h0, h1); ql[kt][3] = bfpack(l0, l1);
        }
    }

    float oc[8][4];
    #pragma unroll
    for (int j = 0; j < 8; j++)
        #pragma unroll
        for (int i = 0; i < 4; i++) oc[j][i] = 0.f;
    float lac0 = 0.f, lac1 = 0.f;    // row g / row g+8 softmax denominators

    const __nv_bfloat16* pkhi = gk_hi + (size_t)bh * SEQ * DK;
    const __nv_bfloat16* pklo = gk_lo + (size_t)bh * SEQ * DK;
    const __nv_bfloat16* pbhi = (finalPass ? gvt_hi : gkt_hi) + (size_t)bh * DK * SEQ;
    const __nv_bfloat16* pblo = (finalPass ? gvt_lo : gkt_lo) + (size_t)bh * DK * SEQ;

    const int lrow = tid >> 2;       // tile-load row 0..63
    const int lseg = tid & 3;        // tile-load 16-col segment

    for (int kt64 = 0; kt64 < SEQ / 64; kt64++) {
        __syncthreads();
        // ---- load K tile (keys x d) and Vals^T tile (d x keys), hi/lo ----
        {
            size_t gk = ((size_t)(kt64 * 64 + lrow)) * DK + lseg * 16;
            uint32_t so = lrow * KSTR + lseg * 16;
            *(uint4*)&s_khi[so]     = *(const uint4*)(pkhi + gk);
            *(uint4*)&s_khi[so + 8] = *(const uint4*)(pkhi + gk + 8);
            *(uint4*)&s_klo[so]     = *(const uint4*)(pklo + gk);
            *(uint4*)&s_klo[so + 8] = *(const uint4*)(pklo + gk + 8);
            size_t gb = (size_t)lrow * SEQ + kt64 * 64 + lseg * 16;
            *(uint4*)&s_vhi[so]     = *(const uint4*)(pbhi + gb);
            *(uint4*)&s_vhi[so + 8] = *(const uint4*)(pbhi + gb + 8);
            *(uint4*)&s_vlo[so]     = *(const uint4*)(pblo + gb);
            *(uint4*)&s_vlo[so + 8] = *(const uint4*)(pblo + gb + 8);
        }
        __syncthreads();

        // ---- S = Q K^T (raw dot products; scale applied in exp) ----
        float sc[8][4];
        #pragma unroll
        for (int j = 0; j < 8; j++)
            #pragma unroll
            for (int i = 0; i < 4; i++) sc[j][i] = 0.f;

        #pragma unroll
        for (int j = 0; j < 8; j++) {
            int key = 8 * j + g;
            #pragma unroll
            for (int kk = 0; kk < 4; kk++) {
                int kc = 16 * kk + 2 * t;
                uint32_t bh0 = *(const uint32_t*)&s_khi[key * KSTR + kc];
                uint32_t bh1 = *(const uint32_t*)&s_khi[key * KSTR + kc + 8];
                uint32_t bl0 = *(const uint32_t*)&s_klo[key * KSTR + kc];
                uint32_t bl1 = *(const uint32_t*)&s_klo[key * KSTR + kc + 8];
                mma16816(sc[j], qh[kk], bh0, bh1);
                mma16816(sc[j], ql[kk], bh0, bh1);
                mma16816(sc[j], qh[kk], bl0, bl1);
            }
        }

        // ---- softmax (fixed max 8) + pack P into A-fragments ----
        uint32_t pah[4][4], pal[4][4];
        #pragma unroll
        for (int kk = 0; kk < 4; kk++) {
            float e0a = __expf(fmaf(sc[2*kk][0],   0.125f, -8.f));
            float e0b = __expf(fmaf(sc[2*kk][1],   0.125f, -8.f));
            float e0c = __expf(fmaf(sc[2*kk][2],   0.125f, -8.f));
            float e0d = __expf(fmaf(sc[2*kk][3],   0.125f, -8.f));
            float e1a = __expf(fmaf(sc[2*kk+1][0], 0.125f, -8.f));
            float e1b = __expf(fmaf(sc[2*kk+1][1], 0.125f, -8.f));
            float e1c = __expf(fmaf(sc[2*kk+1][2], 0.125f, -8.f));
            float e1d = __expf(fmaf(sc[2*kk+1][3], 0.125f, -8.f));
            lac0 += e0a + e0b + e1a + e1b;   // row g
            lac1 += e0c + e0d + e1c + e1d;   // row g+8
            float h0, l0, h1, l1;
            hilo(e0a, h0, l0); hilo(e0b, h1, l1);
            pah[kk][0] = bfpack(h0, h1); pal[kk][0] = bfpack(l0, l1);
            hilo(e0c, h0, l0); hilo(e0d, h1, l1);
            pah[kk][1] = bfpack(h0, h1); pal[kk][1] = bfpack(l0, l1);
            hilo(e1a, h0, l0); hilo(e1b, h1, l1);
            pah[kk][2] = bfpack(h0, h1); pal[kk][2] = bfpack(l0, l1);
            hilo(e1c, h0, l0); hilo(e1d, h1, l1);
            pah[kk][3] = bfpack(h0, h1); pal[kk][3] = bfpack(l0, l1);
        }

        // ---- O += P @ Vals ----
        #pragma unroll
        for (int j = 0; j < 8; j++) {
            int dd = 8 * j + g;
            #pragma unroll
            for (int kk = 0; kk < 4; kk++) {
                int kc = 16 * kk + 2 * t;
                uint32_t vh0 = *(const uint32_t*)&s_vhi[dd * KSTR + kc];
                uint32_t vh1 = *(const uint32_t*)&s_vhi[dd * KSTR + kc + 8];
                uint32_t vl0 = *(const uint32_t*)&s_vlo[dd * KSTR + kc];
                uint32_t vl1 = *(const uint32_t*)&s_vlo[dd * KSTR + kc + 8];
                mma16816(oc[j], pah[kk], vh0, vh1);
                mma16816(oc[j], pal[kk], vh0, vh1);
                mma16816(oc[j], pah[kk], vl0, vl1);
            }
        }
    }

    // ---- epilogue: normalize, store, ssq ----
    lac0 += __shfl_xor_sync(~0u, lac0, 1);
    lac0 += __shfl_xor_sync(~0u, lac0, 2);
    lac1 += __shfl_xor_sync(~0u, lac1, 1);
    lac1 += __shfl_xor_sync(~0u, lac1, 2);
    const float inv0 = 1.0f / lac0;
    const float inv1 = 1.0f / lac1;

    float* ob0 = g_nq + ((size_t)bh * SEQ + q0 + m0 + g) * DK;
    float* ob1 = g_nq + ((size_t)bh * SEQ + q0 + m0 + g + 8) * DK;
    const float* qr0 = qb + (size_t)(m0 + g) * DK;
    const float* qr1 = qb + (size_t)(m0 + g + 8) * DK;
    float local = 0.f;
    #pragma unroll
    for (int j = 0; j < 8; j++) {
        int c = 8 * j + 2 * t;
        float2 w0 = make_float2(oc[j][0] * inv0, oc[j][1] * inv0);
        float2 w1 = make_float2(oc[j][2] * inv1, oc[j][3] * inv1);
        *(float2*)(ob0 + c) = w0;
        *(float2*)(ob1 + c) = w1;
        if (!finalPass) {
            float2 a = *(const float2*)(qr0 + c);
            float2 b = *(const float2*)(qr1 + c);
            float d0 = w0.x - a.x, d1 = w0.y - a.y;
            float d2 = w1.x - b.x, d3 = w1.y - b.y;
            local += d0 * d0 + d1 * d1 + d2 * d2 + d3 * d3;
        }
    }
    if (!finalPass) {
        #pragma unroll
        for (int off = 16; off; off >>= 1)
            local += __shfl_xor_sync(~0u, local, off);
        if (lane == 0) atomicAdd(&g_ssq, local);
    }
}

// ---------------------------------------------------------------------------
__global__ void reset_ssq_kernel() { g_ssq = 0.0f; }

__global__ __launch_bounds__(256)
void gate_kernel()
{
    bool upd = g_ssq > 1e-8f;   // ||diff|| > 1e-4
    int idx = blockIdx.x * blockDim.x + threadIdx.x;
    if (upd) ((float4*)g_q)[idx] = ((const float4*)g_nq)[idx];
}

// ---------------------------------------------------------------------------
// Output projection (R3, passing).
// ---------------------------------------------------------------------------
__global__ __launch_bounds__(128)
void out_gemm(const float* __restrict__ Wo, const float* __restrict__ bo,
              float* __restrict__ C)
{
    __shared__ float As[32 * 128];
    __shared__ float Bs[32 * 64];

    const int n0   = blockIdx.y * 64;
    const int row0 = blockIdx.x * 128;
    const int tid = threadIdx.x;
    const int tx = tid & 7, ty = tid >> 3;

    const int t = row0 + tid;
    const int b = t >> 10, sdx = t & 1023;

    u64 acc2[4][8];
    #pragma unroll
    for (int ip = 0; ip < 4; ip++)
        #pragma unroll
        for (int j = 0; j < 8; j++) acc2[ip][j] = 0ull;

    for (int k0 = 0; k0 < DMODEL; k0 += 32) {
        __syncthreads();
        {
            int h = k0 >> 6, dbase = k0 & 63;
            const float4* ar = (const float4*)(g_nq +
                (((size_t)b * NHEADS + h) * SEQ + sdx) * DK + dbase);
            #pragma unroll
            for (int rep = 0; rep < 8; rep++) {
                float4 v = ar[rep];
                int d = rep * 4;
                As[(d + 0) * 128 + tid] = v.x;
                As[(d + 1) * 128 + tid] = v.y;
                As[(d + 2) * 128 + tid] = v.z;
                As[(d + 3) * 128 + tid] = v.w;
            }
        }
        #pragma unroll
        for (int rep = 0; rep < 4; rep++) {
            int idx = tid + 128 * rep;
            int kb = idx >> 4, nc = (idx & 15) * 4;
            *(float4*)&Bs[kb * 64 + nc] =
                *(const float4*)(Wo + (size_t)(k0 + kb) * DMODEL + n0 + nc);
        }
        __syncthreads();

        #pragma unroll 8
        for (int kk = 0; kk < 32; kk++) {
            ulonglong2 a01 = *(const ulonglong2*)&As[kk * 128 + ty * 8];
            ulonglong2 a23 = *(const ulonglong2*)&As[kk * 128 + ty * 8 + 4];
            u64 ap[4] = {a01.x, a01.y, a23.x, a23.y};
            float4 b0 = *(const float4*)&Bs[kk * 64 + tx * 8];
            float4 b1 = *(const float4*)&Bs[kk * 64 + tx * 8 + 4];
            float bf[8] = {b0.x, b0.y, b0.z, b0.w, b1.x, b1.y, b1.z, b1.w};
            #pragma unroll
            for (int j = 0; j < 8; j++) {
                u64 bb = pack2(bf[j], bf[j]);
                #pragma unroll
                for (int ip = 0; ip < 4; ip++) fma2(acc2[ip][j], ap[ip], bb);
            }
        }
    }

    float v[8][8];
    #pragma unroll
    for (int ip = 0; ip < 4; ip++)
        #pragma unroll
        for (int j = 0; j < 8; j++)
            unpack2(acc2[ip][j], v[2 * ip][j], v[2 * ip + 1][j]);

    float bi[8];
    #pragma unroll
    for (int j = 0; j < 8; j++) bi[j] = bo[n0 + tx * 8 + j];

    #pragma unroll
    for (int i = 0; i < 8; i++) {
        int tr = row0 + ty * 8 + i;
        float* dst = C + (size_t)tr * DMODEL + n0 + tx * 8;
        *(float4*)dst = make_float4(v[i][0] + bi[0], v[i][1] + bi[1],
                                    v[i][2] + bi[2], v[i][3] + bi[3]);
        *(float4*)(dst + 4) = make_float4(v[i][4] + bi[4], v[i][5] + bi[5],
                                          v[i][6] + bi[6], v[i][7] + bi[7]);
    }
}

// ---------------------------------------------------------------------------
extern "C" void kernel_launch(void* const* d_in, const int* in_sizes, int n_in,
                              void* d_out, int out_size)
{
    const float* x     = (const float*)d_in[0];
    const float* Wq    = (const float*)d_in[1];
    const float* bq    = (const float*)d_in[2];
    const float* Wk    = (const float*)d_in[3];
    const float* bk    = (const float*)d_in[4];
    const float* Wv    = (const float*)d_in[5];
    const float* bv    = (const float*)d_in[6];
    const float* Wo    = (const float*)d_in[7];
    const float* bo    = (const float*)d_in[8];
    const float* gamma = (const float*)d_in[9];
    const float* beta  = (const float*)d_in[10];
    float* out = (float*)d_out;

    // 1. QKV projections (+ fused LayerNorm for q,k)
    qkv_gemm<<<dim3(TOKENS / 128, 24), 128>>>(x, Wq, bq, Wk, bk, Wv, bv,
                                              gamma, beta);
    // 2. One-time bf16 hi/lo splits of K, K^T, V^T
    prep_kernel<<<dim3(SEQ / 64, BHD), 256>>>();
    // 3. Hopfield update iterations (values = K) with exact eps gating
    for (int it = 0; it < 3; it++) {
        reset_ssq_kernel<<<1, 1>>>();
        attn_mma<<<dim3(SEQ / 128, BHD), 256>>>(0);
        gate_kernel<<<QKV_ELEMS / 4 / 256, 256>>>();
    }
    // 4. Final retrieval (values = V)
    attn_mma<<<dim3(SEQ / 128, BHD), 256>>>(1);
    // 5. Output projection
    out_gemm<<<dim3(TOKENS / 128, DMODEL / 64), 128>>>(Wo, bo, out);
}